// round 16
// baseline (speedup 1.0000x reference)
#include <cuda_runtime.h>
#include <cuda_fp16.h>
#include <cstdint>

// Problem constants: B=8, L=K=2048, D=32, SIGMA=1, EPS=1, 10 iters.
// Sparse formulation: H = e^t = 1 + expm1(t), t = exp(-||x-y||^2/2), t
// significant only for ||x-y||^2 < DIST_CUT. Row logsumexp = dense scalar W +
// sparse fixups. Dots on tensor cores (HMMA m16n8k16).
// Sinkhorn runs in e-space: e_i = exp(gw_i + f_i);
//   f' = 0.5f - 0.5 log(W + S_i)  <=>  e' = sqrt(u_i e_i) * rsqrt(W + S_i)
// with rsqrt(W+S) = rsqrt(W) * (1+z)^(-1/2), z = S_i/W (3-term poly).
// => 1 MUFU (sqrt) per element per phase instead of exp+log.
#define BB 8
#define NN 2048
#define DD 32
#define CAP (1u << 18)
#define DIST_CUT 20.0f
#define SX 40              // SMEM row stride in halves (80B, 16B-aligned rows)

// ---------------- device scratch ----------------
static __device__ unsigned g_cnt[3][BB];       // zero at load; re-zeroed by k_iter
static __device__ unsigned g_pl[3][BB][CAP];   // (row<<16) | col
static __device__ float    g_pv[3][BB][CAP];   // c = expm1(exp(-dist/2))
static __device__ float    g_part[3][BB];      // per-chain output partials

// ---------------- math helpers ----------------
__device__ __forceinline__ float sqrt_ap(float x) {
    float r; asm("sqrt.approx.f32 %0, %1;" : "=f"(r) : "f"(x)); return r;
}
__device__ __forceinline__ float rsqrt_ap(float x) {
    float r; asm("rsqrt.approx.f32 %0, %1;" : "=f"(r) : "f"(x)); return r;
}

// ---------------- mma helpers ----------------
__device__ __forceinline__ void ldsm_x4(uint32_t* r, const __half* p) {
    unsigned addr = (unsigned)__cvta_generic_to_shared(p);
    asm volatile("ldmatrix.sync.aligned.m8n8.x4.shared.b16 {%0,%1,%2,%3}, [%4];"
                 : "=r"(r[0]), "=r"(r[1]), "=r"(r[2]), "=r"(r[3]) : "r"(addr));
}
__device__ __forceinline__ void mma16816(float* d, const uint32_t* a,
                                         const uint32_t* b, const float* c) {
    asm volatile(
        "mma.sync.aligned.m16n8k16.row.col.f32.f16.f16.f32 "
        "{%0,%1,%2,%3}, {%4,%5,%6,%7}, {%8,%9}, {%10,%11,%12,%13};"
        : "=f"(d[0]), "=f"(d[1]), "=f"(d[2]), "=f"(d[3])
        : "r"(a[0]), "r"(a[1]), "r"(a[2]), "r"(a[3]), "r"(b[0]), "r"(b[1]),
          "f"(c[0]), "f"(c[1]), "f"(c[2]), "f"(c[3]));
}

__device__ __forceinline__ void emit(int m, int b, unsigned r, unsigned q,
                                     float dist, bool sym, bool mir) {
    float c;
    if (sym && r == q) c = 1.71828183f;              // diagonal: exact e-1
    else {
        float t = __expf(-0.5f * fmaxf(dist, 0.f));
        c = expm1f(t);
    }
    unsigned idx = atomicAdd(&g_cnt[m][b], mir ? 2u : 1u);
    if (idx < CAP) { g_pl[m][b][idx] = (r << 16) | q; g_pv[m][b][idx] = c; }
    if (mir && idx + 1 < CAP) {
        g_pl[m][b][idx + 1] = (q << 16) | r;
        g_pv[m][b][idx + 1] = c;
    }
}

// ---------------- sparse pair extraction (tensor-core dots) ----------------
// 128x128 tile per block, 256 threads (8 warps). B fragments fetched for two
// n-tiles at once via ldmatrix.x4 (halves ldsm count vs x2).
__global__ __launch_bounds__(256) void k_sparse(const float* __restrict__ x,
                                                const float* __restrict__ y) {
    __shared__ __half sXt[128 * SX];
    __shared__ __half sYt[128 * SX];
    __shared__ float snr[128], snc[128];
    int m = blockIdx.y >> 4, ty = blockIdx.y & 15;
    int bx = blockIdx.x, b = blockIdx.z;
    int sym = (m != 1);
    if (sym && bx > ty) return;

    const float* Rm = (m == 0) ? x : y;
    const float* Cm = (m == 2) ? y : x;
    int r0 = ty * 128, c0 = bx * 128;
    const float* Rb = Rm + ((size_t)b * NN + r0) * DD;
    const float* Cb = Cm + ((size_t)b * NN + c0) * DD;
    int tid = threadIdx.x;

    for (int i = tid; i < 128 * 16; i += 256) {
        int row = i >> 4, d2 = i & 15;
        float2 rv = *(const float2*)&Rb[row * DD + 2 * d2];
        float2 cv = *(const float2*)&Cb[row * DD + 2 * d2];
        *(__half2*)&sXt[row * SX + 2 * d2] = __floats2half2_rn(rv.x, rv.y);
        *(__half2*)&sYt[row * SX + 2 * d2] = __floats2half2_rn(cv.x, cv.y);
    }
    __syncthreads();

    {
        int row = tid & 127;
        const __half2* p = (const __half2*)((tid < 128 ? sXt : sYt) + row * SX);
        float s = 0.f;
#pragma unroll
        for (int d2 = 0; d2 < 16; d2++) {
            float2 v = __half22float2(p[d2]);
            s = fmaf(v.x, v.x, fmaf(v.y, v.y, s));
        }
        if (tid < 128) snr[row] = s; else snc[row] = s;
    }
    __syncthreads();

    int warp = tid >> 5, lane = tid & 31;
    int rw = warp * 16;

    uint32_t a0[4], a1[4];
    {
        int sub = lane >> 3, tt = lane & 7;
        int arow = rw + (sub & 1) * 8 + tt;
        int koff = (sub >> 1) * 8;
        ldsm_x4(a0, &sXt[arow * SX + koff]);
        ldsm_x4(a1, &sXt[arow * SX + 16 + koff]);
    }

    bool mir = sym && (bx != ty);
    int g = lane >> 2, tig = lane & 3;
    int lr0 = rw + g, lr1 = lr0 + 8;
    float nr0 = snr[lr0], nr1 = snr[lr1];

    // B address pattern for x4 over two n-tiles: lanes 0-7 -> nt0 k+0,
    // 8-15 -> nt0 k+8, 16-23 -> nt1 k+0, 24-31 -> nt1 k+8.
    int l8 = lane & 7, sel2 = lane >> 3;
    int brow_off = (sel2 >> 1) * 8 + l8;
    int bk_off = (sel2 & 1) * 8;

#pragma unroll
    for (int p2 = 0; p2 < 8; p2++) {
        int n0 = p2 * 16;
        uint32_t bA[4], bB[4];
        ldsm_x4(bA, &sYt[(n0 + brow_off) * SX + bk_off]);        // k0-15, nt0+nt1
        ldsm_x4(bB, &sYt[(n0 + brow_off) * SX + 16 + bk_off]);   // k16-31
#pragma unroll
        for (int h = 0; h < 2; h++) {
            float d[4] = {0.f, 0.f, 0.f, 0.f};
            mma16816(d, a0, &bA[2 * h], d);
            mma16816(d, a1, &bB[2 * h], d);
            int nb = n0 + 8 * h;
            int lc0 = nb + 2 * tig, lc1 = lc0 + 1;
            float nc0 = snc[lc0], nc1 = snc[lc1];
            float di;
            di = nr0 + nc0 - 2.f * d[0];
            if (di < DIST_CUT) emit(m, b, r0 + lr0, c0 + lc0, di, sym, mir);
            di = nr0 + nc1 - 2.f * d[1];
            if (di < DIST_CUT) emit(m, b, r0 + lr0, c0 + lc1, di, sym, mir);
            di = nr1 + nc0 - 2.f * d[2];
            if (di < DIST_CUT) emit(m, b, r0 + lr1, c0 + lc0, di, sym, mir);
            di = nr1 + nc1 - 2.f * d[3];
            if (di < DIST_CUT) emit(m, b, r0 + lr1, c0 + lc1, di, sym, mir);
        }
    }
}

// ---------------- Sinkhorn chains in e-space ----------------

__device__ __forceinline__ float wred(float v) {
#pragma unroll
    for (int o = 16; o; o >>= 1) v += __shfl_xor_sync(0xffffffffu, v, o);
    return v;
}

// S[dst] += c * eS[src]
__device__ __forceinline__ void sparse_add(int m, int b, int tr,
                                           const float* eS, float* S) {
    unsigned cnt = g_cnt[m][b];
    if (cnt > CAP) cnt = CAP;
    for (unsigned u = threadIdx.x; u < cnt; u += 1024) {
        unsigned p = g_pl[m][b][u];
        float c = g_pv[m][b][u];
        unsigned r = p >> 16, q = p & 0xffffu;
        if (tr) atomicAdd(&S[q], c * eS[r]);
        else    atomicAdd(&S[r], c * eS[q]);
    }
}

// Compute W = sum eS + fill S with sparse fixups. red[32]=W, [33]=rsW, [34]=invW.
__device__ __forceinline__ float gatherW(int m, int b, int tr,
                                         const float* eS, float* S, float* red) {
    int tid = threadIdx.x, w = tid >> 5, lane = tid & 31;
    __syncthreads();                 // eS, S(zeroed) ready
    float p = eS[tid] + eS[tid + 1024];
    p = wred(p);
    if (!lane) red[w] = p;
    sparse_add(m, b, tr, eS, S);
    __syncthreads();
    if (w == 0) {
        float v = red[lane];
        v = wred(v);
        if (!lane) {
            float rsW = rsqrt_ap(v);
            red[32] = v; red[33] = rsW; red[34] = rsW * rsW;   // 1/W
        }
    }
    __syncthreads();
    return red[32];
}

// One Sinkhorn phase: e-state update eD' = sqrt(uD*eD) * rsqrt(W + S).
__device__ __forceinline__ void phaseE(int m, int b, int tr,
                                       const float* eS, float* eD,
                                       const float* uD, float* S, float* red) {
    gatherW(m, b, tr, eS, S, red);
    float rsW = red[33], invW = red[34];
    int tid = threadIdx.x;
#pragma unroll
    for (int k = 0; k < 2; k++) {
        int i = tid + k * 1024;
        float z = S[i] * invW;
        float rp;
        if (z > 0.08f) rp = rsqrt_ap(1.f + z);      // rare
        else rp = 1.f + z * (-0.5f + z * (0.375f - 0.3125f * z));
        eD[i] = sqrt_ap(uD[i] * eD[i]) * (rsW * rp);
        S[i] = 0.f;
    }
}

// grid (3, BB): blockIdx.x = chain (0: xx, 1: yy, 2: yx/xy), blockIdx.y = batch.
__global__ __launch_bounds__(1024) void k_iter(const float* __restrict__ a,
                                               const float* __restrict__ bw,
                                               float* __restrict__ out) {
    extern __shared__ float sm[];
    __shared__ float red[40];
    float* eA = sm;            // chain<2: the e vector; chain3: exp(a+fxy)
    float* eB = sm + NN;       // chain3: exp(b+fyx)
    float* S  = sm + 2 * NN;
    float* S2 = sm + 3 * NN;
    float* uA = sm + 4 * NN;   // exp(a) (chain yy: exp(b))
    float* uB = sm + 5 * NN;   // exp(b)
    int sel = blockIdx.x, b = blockIdx.y;
    int tid = threadIdx.x, w = tid >> 5, lane = tid & 31;
    const float* ga = a + b * NN;
    const float* gb = bw + b * NN;

    float part = 0.f;
    int m;
    if (sel < 2) {
        m = sel ? 2 : 0;
        const float* gw = sel ? gb : ga;
#pragma unroll
        for (int k = 0; k < 2; k++) {
            int i = tid + k * 1024;
            float u = __expf(gw[i]);
            uA[i] = u; eA[i] = u; S[i] = 0.f;
        }
        for (int t = 0; t < 10; t++)
            phaseE(m, b, 0, eA, eA, uA, S, red);
        float W = gatherW(m, b, 0, eA, S, red);    // final corrections in S
#pragma unroll
        for (int k = 0; k < 2; k++) {
            int i = tid + k * 1024;
            part += __logf(W + S[i]) * uA[i];
        }
    } else {
        m = 1;
#pragma unroll
        for (int k = 0; k < 2; k++) {
            int i = tid + k * 1024;
            float ua = __expf(ga[i]), ub = __expf(gb[i]);
            uA[i] = ua; uB[i] = ub;
            eA[i] = ua; eB[i] = ub;       // f = 0 initially
            S[i] = 0.f; S2[i] = 0.f;
        }
        for (int t = 0; t < 10; t++) {
            phaseE(1, b, 0, eA, eB, uB, S, red);   // fyx update, src exp(a+fxy)
            phaseE(1, b, 1, eB, eA, uA, S, red);   // fxy update, src NEW exp(b+fyx)
        }
        float W1 = gatherW(1, b, 0, eA, S, red);   // fe_yx corrections
        float W2 = gatherW(1, b, 1, eB, S2, red);  // fe_xy corrections
#pragma unroll
        for (int k = 0; k < 2; k++) {
            int i = tid + k * 1024;
            part += (-__logf(W2 + S2[i])) * uA[i] + (-__logf(W1 + S[i])) * uB[i];
        }
    }

    part = wred(part);
    if (!lane) red[w] = part;
    __syncthreads();
    if (w == 0) {
        float v = red[lane];
        v = wred(v);
        if (!lane) g_part[sel][b] = v;
    }
    if (tid == 0) g_cnt[m][b] = 0;   // re-zero for the next graph replay
}

// out[b] = g_part[0][b] + g_part[1][b] + g_part[2][b]   (EPSILON = 1)
__global__ void k_out(float* __restrict__ out) {
    int b = threadIdx.x;
    if (b < BB) out[b] = g_part[0][b] + g_part[1][b] + g_part[2][b];
}

// ---------------- launch ----------------
extern "C" void kernel_launch(void* const* d_in, const int* in_sizes, int n_in,
                              void* d_out, int out_size) {
    const float* x = (const float*)d_in[0];   // (8, 2048, 32)
    const float* a = (const float*)d_in[1];   // (8, 2048)
    const float* y = (const float*)d_in[2];   // (8, 2048, 32)
    const float* b = (const float*)d_in[3];   // (8, 2048)
    float* out = (float*)d_out;               // (8,)

    cudaFuncSetAttribute(k_iter, cudaFuncAttributeMaxDynamicSharedMemorySize,
                         6 * NN * (int)sizeof(float));
    k_sparse<<<dim3(16, 48, BB), 256>>>(x, y);
    k_iter<<<dim3(3, BB), 1024, 6 * NN * sizeof(float)>>>(a, b, out);
    k_out<<<1, 32>>>(out);
}

// round 17
// speedup vs baseline: 1.2009x; 1.2009x over previous
#include <cuda_runtime.h>
#include <cuda_fp16.h>
#include <cstdint>

// Problem constants: B=8, L=K=2048, D=32, SIGMA=1, EPS=1, 10 iters.
// Sparse formulation: H = e^t = 1 + expm1(t), t = exp(-||x-y||^2/2), t
// significant only for ||x-y||^2 < DIST_CUT. Row logsumexp = dense scalar W +
// sparse fixups. Dots on tensor cores (HMMA m16n8k16, R15 proven pattern).
// Sinkhorn in e-space: e' = sqrt(u*e) * rsqrt(W + S) (1 MUFU/elem/phase).
#define BB 8
#define NN 2048
#define DD 32
#define CAP (1u << 18)
#define DIST_CUT 20.0f
#define SX 40              // SMEM row stride in halves (80B, 16B-aligned rows)

// ---------------- device scratch ----------------
static __device__ unsigned g_cnt[3][BB];       // zero at load; re-zeroed by k_iter
static __device__ unsigned g_pl[3][BB][CAP];   // (row<<16) | col
static __device__ float    g_pv[3][BB][CAP];   // c = expm1(exp(-dist/2))
static __device__ float    g_part[3][BB];      // per-chain output partials
static __device__ unsigned g_done[BB];         // arrival counter per batch

// ---------------- math helpers ----------------
__device__ __forceinline__ float sqrt_ap(float x) {
    float r; asm("sqrt.approx.f32 %0, %1;" : "=f"(r) : "f"(x)); return r;
}
__device__ __forceinline__ float rsqrt_ap(float x) {
    float r; asm("rsqrt.approx.f32 %0, %1;" : "=f"(r) : "f"(x)); return r;
}

// ---------------- mma helpers ----------------
__device__ __forceinline__ void ldsm_x4(uint32_t* r, const __half* p) {
    unsigned addr = (unsigned)__cvta_generic_to_shared(p);
    asm volatile("ldmatrix.sync.aligned.m8n8.x4.shared.b16 {%0,%1,%2,%3}, [%4];"
                 : "=r"(r[0]), "=r"(r[1]), "=r"(r[2]), "=r"(r[3]) : "r"(addr));
}
__device__ __forceinline__ void ldsm_x2(uint32_t* r, const __half* p) {
    unsigned addr = (unsigned)__cvta_generic_to_shared(p);
    asm volatile("ldmatrix.sync.aligned.m8n8.x2.shared.b16 {%0,%1}, [%2];"
                 : "=r"(r[0]), "=r"(r[1]) : "r"(addr));
}
__device__ __forceinline__ void mma16816(float* d, const uint32_t* a,
                                         const uint32_t* b, const float* c) {
    asm volatile(
        "mma.sync.aligned.m16n8k16.row.col.f32.f16.f16.f32 "
        "{%0,%1,%2,%3}, {%4,%5,%6,%7}, {%8,%9}, {%10,%11,%12,%13};"
        : "=f"(d[0]), "=f"(d[1]), "=f"(d[2]), "=f"(d[3])
        : "r"(a[0]), "r"(a[1]), "r"(a[2]), "r"(a[3]), "r"(b[0]), "r"(b[1]),
          "f"(c[0]), "f"(c[1]), "f"(c[2]), "f"(c[3]));
}

__device__ __forceinline__ void emit(int m, int b, unsigned r, unsigned q,
                                     float dist, bool sym, bool mir) {
    float c;
    if (sym && r == q) c = 1.71828183f;              // diagonal: exact e-1
    else {
        float t = __expf(-0.5f * fmaxf(dist, 0.f));
        c = expm1f(t);
    }
    unsigned idx = atomicAdd(&g_cnt[m][b], mir ? 2u : 1u);
    if (idx < CAP) { g_pl[m][b][idx] = (r << 16) | q; g_pv[m][b][idx] = c; }
    if (mir && idx + 1 < CAP) {
        g_pl[m][b][idx + 1] = (q << 16) | r;
        g_pv[m][b][idx + 1] = c;
    }
}

// ---------------- sparse pair extraction (R15-proven tensor-core shape) ----
// 128x128 tile per block, 256 threads (8 warps, 16 rows each). X/Y tiles in
// SMEM as half [row][d] stride SX. blockIdx.y: m = y>>4, ty = y&15.
__global__ __launch_bounds__(256) void k_sparse(const float* __restrict__ x,
                                                const float* __restrict__ y) {
    __shared__ __half sXt[128 * SX];
    __shared__ __half sYt[128 * SX];
    __shared__ float snr[128], snc[128];
    int m = blockIdx.y >> 4, ty = blockIdx.y & 15;
    int bx = blockIdx.x, b = blockIdx.z;
    int sym = (m != 1);
    if (sym && bx > ty) return;

    const float* Rm = (m == 0) ? x : y;
    const float* Cm = (m == 2) ? y : x;
    int r0 = ty * 128, c0 = bx * 128;
    const float* Rb = Rm + ((size_t)b * NN + r0) * DD;
    const float* Cb = Cm + ((size_t)b * NN + c0) * DD;
    int tid = threadIdx.x;

    // stage fp32 -> half
    for (int i = tid; i < 128 * 16; i += 256) {
        int row = i >> 4, d2 = i & 15;
        float2 rv = *(const float2*)&Rb[row * DD + 2 * d2];
        float2 cv = *(const float2*)&Cb[row * DD + 2 * d2];
        *(__half2*)&sXt[row * SX + 2 * d2] = __floats2half2_rn(rv.x, rv.y);
        *(__half2*)&sYt[row * SX + 2 * d2] = __floats2half2_rn(cv.x, cv.y);
    }
    __syncthreads();

    // norms from staged half data (consistent rounding with the dots)
    {
        int row = tid & 127;
        const __half2* p = (const __half2*)((tid < 128 ? sXt : sYt) + row * SX);
        float s = 0.f;
#pragma unroll
        for (int d2 = 0; d2 < 16; d2++) {
            float2 v = __half22float2(p[d2]);
            s = fmaf(v.x, v.x, fmaf(v.y, v.y, s));
        }
        if (tid < 128) snr[row] = s; else snc[row] = s;
    }
    __syncthreads();

    int warp = tid >> 5, lane = tid & 31;
    int rw = warp * 16;

    // A fragments for this warp's 16 rows, both k-steps
    uint32_t a0[4], a1[4];
    {
        int sub = lane >> 3, tt = lane & 7;
        int arow = rw + (sub & 1) * 8 + tt;
        int koff = (sub >> 1) * 8;
        ldsm_x4(a0, &sXt[arow * SX + koff]);
        ldsm_x4(a1, &sXt[arow * SX + 16 + koff]);
    }

    bool mir = sym && (bx != ty);
    int g = lane >> 2, tig = lane & 3;

    // 16 col-tiles of n8
#pragma unroll 4
    for (int nt = 0; nt < 16; nt++) {
        int n0 = nt * 8;
        uint32_t b0[2], b1[2];
        {
            int bl = lane & 7, bk = ((lane >> 3) & 1) * 8;
            ldsm_x2(b0, &sYt[(n0 + bl) * SX + bk]);
            ldsm_x2(b1, &sYt[(n0 + bl) * SX + 16 + bk]);
        }
        float d[4] = {0.f, 0.f, 0.f, 0.f};
        mma16816(d, a0, b0, d);
        mma16816(d, a1, b1, d);

        // epilogue: D fragment m16n8 f32 standard mapping
        int lr0 = rw + g, lr1 = lr0 + 8;
        int lc0 = n0 + 2 * tig, lc1 = lc0 + 1;
        float nr0 = snr[lr0], nr1 = snr[lr1];
        float nc0 = snc[lc0], nc1 = snc[lc1];
        float di;
        di = nr0 + nc0 - 2.f * d[0];
        if (di < DIST_CUT) emit(m, b, r0 + lr0, c0 + lc0, di, sym, mir);
        di = nr0 + nc1 - 2.f * d[1];
        if (di < DIST_CUT) emit(m, b, r0 + lr0, c0 + lc1, di, sym, mir);
        di = nr1 + nc0 - 2.f * d[2];
        if (di < DIST_CUT) emit(m, b, r0 + lr1, c0 + lc0, di, sym, mir);
        di = nr1 + nc1 - 2.f * d[3];
        if (di < DIST_CUT) emit(m, b, r0 + lr1, c0 + lc1, di, sym, mir);
    }
}

// ---------------- Sinkhorn chains in e-space ----------------

__device__ __forceinline__ float wred(float v) {
#pragma unroll
    for (int o = 16; o; o >>= 1) v += __shfl_xor_sync(0xffffffffu, v, o);
    return v;
}

// S[dst] += c * eS[src]
__device__ __forceinline__ void sparse_add(int m, int b, int tr,
                                           const float* eS, float* S) {
    unsigned cnt = g_cnt[m][b];
    if (cnt > CAP) cnt = CAP;
    for (unsigned u = threadIdx.x; u < cnt; u += 1024) {
        unsigned p = g_pl[m][b][u];
        float c = g_pv[m][b][u];
        unsigned r = p >> 16, q = p & 0xffffu;
        if (tr) atomicAdd(&S[q], c * eS[r]);
        else    atomicAdd(&S[r], c * eS[q]);
    }
}

// W = sum eS + sparse fixups into S. red[32]=W, [33]=rsqrt(W), [34]=1/W.
__device__ __forceinline__ float gatherW(int m, int b, int tr,
                                         const float* eS, float* S, float* red) {
    int tid = threadIdx.x, w = tid >> 5, lane = tid & 31;
    __syncthreads();                 // eS, S(zeroed) ready
    float p = eS[tid] + eS[tid + 1024];
    p = wred(p);
    if (!lane) red[w] = p;
    sparse_add(m, b, tr, eS, S);
    __syncthreads();
    if (w == 0) {
        float v = red[lane];
        v = wred(v);
        if (!lane) {
            float rsW = rsqrt_ap(v);
            red[32] = v; red[33] = rsW; red[34] = rsW * rsW;
        }
    }
    __syncthreads();
    return red[32];
}

// One Sinkhorn phase: eD' = sqrt(uD*eD) * rsqrt(W + S).
__device__ __forceinline__ void phaseE(int m, int b, int tr,
                                       const float* eS, float* eD,
                                       const float* uD, float* S, float* red) {
    gatherW(m, b, tr, eS, S, red);
    float rsW = red[33], invW = red[34];
    int tid = threadIdx.x;
#pragma unroll
    for (int k = 0; k < 2; k++) {
        int i = tid + k * 1024;
        float z = S[i] * invW;
        float rp;
        if (z > 0.08f) rp = rsqrt_ap(1.f + z);      // rare
        else rp = 1.f + z * (-0.5f + z * (0.375f - 0.3125f * z));
        eD[i] = sqrt_ap(uD[i] * eD[i]) * (rsW * rp);
        S[i] = 0.f;
    }
}

// grid (3, BB): blockIdx.x = chain (0: xx, 1: yy, 2: yx/xy), blockIdx.y = batch.
// The last chain CTA per batch combines partials into out[b].
__global__ __launch_bounds__(1024) void k_iter(const float* __restrict__ a,
                                               const float* __restrict__ bw,
                                               float* __restrict__ out) {
    extern __shared__ float sm[];
    __shared__ float red[40];
    float* eA = sm;            // chain<2: the e vector; chain3: exp(a+fxy)
    float* eB = sm + NN;       // chain3: exp(b+fyx)
    float* S  = sm + 2 * NN;
    float* S2 = sm + 3 * NN;
    float* uA = sm + 4 * NN;   // exp(a) (chain yy: exp(b))
    float* uB = sm + 5 * NN;   // exp(b)
    int sel = blockIdx.x, b = blockIdx.y;
    int tid = threadIdx.x, w = tid >> 5, lane = tid & 31;
    const float* ga = a + b * NN;
    const float* gb = bw + b * NN;

    float part = 0.f;
    int m;
    if (sel < 2) {
        m = sel ? 2 : 0;
        const float* gw = sel ? gb : ga;
#pragma unroll
        for (int k = 0; k < 2; k++) {
            int i = tid + k * 1024;
            float u = __expf(gw[i]);
            uA[i] = u; eA[i] = u; S[i] = 0.f;
        }
        for (int t = 0; t < 10; t++)
            phaseE(m, b, 0, eA, eA, uA, S, red);
        float W = gatherW(m, b, 0, eA, S, red);    // final corrections in S
#pragma unroll
        for (int k = 0; k < 2; k++) {
            int i = tid + k * 1024;
            part += __logf(W + S[i]) * uA[i];
        }
    } else {
        m = 1;
#pragma unroll
        for (int k = 0; k < 2; k++) {
            int i = tid + k * 1024;
            float ua = __expf(ga[i]), ub = __expf(gb[i]);
            uA[i] = ua; uB[i] = ub;
            eA[i] = ua; eB[i] = ub;       // f = 0 initially
            S[i] = 0.f; S2[i] = 0.f;
        }
        for (int t = 0; t < 10; t++) {
            phaseE(1, b, 0, eA, eB, uB, S, red);   // fyx update, src exp(a+fxy)
            phaseE(1, b, 1, eB, eA, uA, S, red);   // fxy update, src NEW exp(b+fyx)
        }
        float W1 = gatherW(1, b, 0, eA, S, red);   // fe_yx corrections
        float W2 = gatherW(1, b, 1, eB, S2, red);  // fe_xy corrections
#pragma unroll
        for (int k = 0; k < 2; k++) {
            int i = tid + k * 1024;
            part += (-__logf(W2 + S2[i])) * uA[i] + (-__logf(W1 + S[i])) * uB[i];
        }
    }

    part = wred(part);
    if (!lane) red[w] = part;
    __syncthreads();
    if (w == 0) {
        float v = red[lane];
        v = wred(v);
        if (!lane) {
            g_part[sel][b] = v;
            __threadfence();
            unsigned prev = atomicAdd(&g_done[b], 1u);
            if (prev == 2u) {              // last chain for this batch
                __threadfence();
                out[b] = g_part[0][b] + g_part[1][b] + g_part[2][b];  // EPS=1
                g_done[b] = 0;             // reset for next graph replay
            }
        }
    }
    if (tid == 1) g_cnt[m][b] = 0;   // re-zero counter for the next replay
}

// ---------------- launch ----------------
extern "C" void kernel_launch(void* const* d_in, const int* in_sizes, int n_in,
                              void* d_out, int out_size) {
    const float* x = (const float*)d_in[0];   // (8, 2048, 32)
    const float* a = (const float*)d_in[1];   // (8, 2048)
    const float* y = (const float*)d_in[2];   // (8, 2048, 32)
    const float* b = (const float*)d_in[3];   // (8, 2048)
    float* out = (float*)d_out;               // (8,)

    cudaFuncSetAttribute(k_iter, cudaFuncAttributeMaxDynamicSharedMemorySize,
                         6 * NN * (int)sizeof(float));
    k_sparse<<<dim3(16, 48, BB), 256>>>(x, y);
    k_iter<<<dim3(3, BB), 1024, 6 * NN * sizeof(float)>>>(a, b, out);
}